// round 3
// baseline (speedup 1.0000x reference)
#include <cuda_runtime.h>
#include <cuda_bf16.h>
#include <cstdint>

// DynamicMaskHead: 128 instances, per-instance MLP 10 -> 8 -> 8 -> 1 over
// 160x160 pixels (fp32). 8 pixels/thread, layers 1+2 fused, packed
// fma.rn.f32x2, paired-weight LDS.128, register cap for 5 CTAs/SM.

#define NINST 128
#define CIN   10
#define CMID  8
#define HW    25600          // 160*160
#define HW8   (HW / 8)       // 3200 8-pixel groups per instance
#define TPB   128

__device__ __forceinline__ float2 ffma2(float2 a, float2 b, float2 c) {
    float2 d;
    asm("fma.rn.f32x2 %0, %1, %2, %3;"
        : "=l"(reinterpret_cast<unsigned long long&>(d))
        : "l"(reinterpret_cast<unsigned long long&>(a)),
          "l"(reinterpret_cast<unsigned long long&>(b)),
          "l"(reinterpret_cast<unsigned long long&>(c)));
    return d;
}

__device__ __forceinline__ float2 relu2(float2 a) {
    return make_float2(fmaxf(a.x, 0.0f), fmaxf(a.y, 0.0f));
}

__global__ void __launch_bounds__(TPB, 5)
mask_head_kernel(const float* __restrict__ feat,
                 const float* __restrict__ params,
                 float* __restrict__ out) {
    // Weights duplicated into both float2 halves (one LDS feeds fma.rn.f32x2),
    // and laid out so adjacent weights in the inner loops are contiguous:
    //   w0t: [k][o]  (layer0 loops k outer, o inner -> pair o's per LDS.128)
    //   w1s: [o][k]  (layer1 loops o outer, k inner -> pair k's per LDS.128)
    __shared__ __align__(16) float2 w0t[CIN * CMID];   // 80
    __shared__ __align__(16) float2 w1s[CMID * CMID];  // 64
    __shared__ __align__(16) float2 w2s[CMID];         // 8
    __shared__ float2 b0s[CMID];
    __shared__ float2 b1s[CMID];
    __shared__ float2 b2s;

    const int inst = blockIdx.y;
    const float* p = params + inst * 169;
    for (int i = threadIdx.x; i < 169; i += TPB) {
        float v = p[i];
        float2 vv = make_float2(v, v);
        if (i < 80) {
            int o = i / CIN, k = i % CIN;
            w0t[k * CMID + o] = vv;               // transposed
        }
        else if (i < 144) w1s[i - 80]  = vv;      // [o][k], k contiguous
        else if (i < 152) w2s[i - 144] = vv;
        else if (i < 160) b0s[i - 152] = vv;
        else if (i < 168) b1s[i - 160] = vv;
        else              b2s          = vv;
    }
    __syncthreads();

    const int g8 = blockIdx.x * TPB + threadIdx.x;   // 0 .. HW8-1
    const float4* fbase =
        reinterpret_cast<const float4*>(feat)
        + ((size_t)inst * CIN * HW + (size_t)g8 * 8) / 4;

    // ---- Layer 0 (10 -> 8, ReLU), streaming over input channels ----
    float2 h0[CMID][4];
#pragma unroll
    for (int o = 0; o < CMID; o++) {
        float2 b = b0s[o];
#pragma unroll
        for (int j = 0; j < 4; j++) h0[o][j] = b;
    }

#pragma unroll
    for (int k = 0; k < CIN; k++) {
        float4 v0 = fbase[(size_t)k * (HW / 4)];
        float4 v1 = fbase[(size_t)k * (HW / 4) + 1];
        float2 x[4] = { make_float2(v0.x, v0.y), make_float2(v0.z, v0.w),
                        make_float2(v1.x, v1.y), make_float2(v1.z, v1.w) };
        const float4* w4 = reinterpret_cast<const float4*>(w0t + k * CMID);
#pragma unroll
        for (int op = 0; op < 4; op++) {          // pairs of outputs
            float4 wp = w4[op];
            float2 wlo = make_float2(wp.x, wp.y);
            float2 whi = make_float2(wp.z, wp.w);
#pragma unroll
            for (int j = 0; j < 4; j++) {
                h0[2 * op    ][j] = ffma2(wlo, x[j], h0[2 * op    ][j]);
                h0[2 * op + 1][j] = ffma2(whi, x[j], h0[2 * op + 1][j]);
            }
        }
    }
#pragma unroll
    for (int o = 0; o < CMID; o++)
#pragma unroll
        for (int j = 0; j < 4; j++) h0[o][j] = relu2(h0[o][j]);

    // ---- Layers 1+2 fused: h1[o] computed then folded into final acc ----
    float2 acc[4];
    {
        float2 b = b2s;
#pragma unroll
        for (int j = 0; j < 4; j++) acc[j] = b;
    }

    const float4* w2p = reinterpret_cast<const float4*>(w2s);
#pragma unroll
    for (int op = 0; op < 4; op++) {              // pairs of h1 outputs
        float2 t0[4], t1[4];
        float2 ba = b1s[2 * op], bb = b1s[2 * op + 1];
#pragma unroll
        for (int j = 0; j < 4; j++) { t0[j] = ba; t1[j] = bb; }

        const float4* wa = reinterpret_cast<const float4*>(w1s + (2 * op) * CMID);
        const float4* wb = reinterpret_cast<const float4*>(w1s + (2 * op + 1) * CMID);
#pragma unroll
        for (int kp = 0; kp < 4; kp++) {          // pairs of inputs
            float4 wpa = wa[kp];
            float4 wpb = wb[kp];
            float2 wa0 = make_float2(wpa.x, wpa.y), wa1 = make_float2(wpa.z, wpa.w);
            float2 wb0 = make_float2(wpb.x, wpb.y), wb1 = make_float2(wpb.z, wpb.w);
#pragma unroll
            for (int j = 0; j < 4; j++) {
                t0[j] = ffma2(wa0, h0[2 * kp    ][j], t0[j]);
                t0[j] = ffma2(wa1, h0[2 * kp + 1][j], t0[j]);
                t1[j] = ffma2(wb0, h0[2 * kp    ][j], t1[j]);
                t1[j] = ffma2(wb1, h0[2 * kp + 1][j], t1[j]);
            }
        }
        float4 w2pair = w2p[op];
        float2 w2a = make_float2(w2pair.x, w2pair.y);
        float2 w2b = make_float2(w2pair.z, w2pair.w);
#pragma unroll
        for (int j = 0; j < 4; j++) {
            acc[j] = ffma2(w2a, relu2(t0[j]), acc[j]);
            acc[j] = ffma2(w2b, relu2(t1[j]), acc[j]);
        }
    }

    float4* obase = reinterpret_cast<float4*>(out)
                    + ((size_t)inst * HW + (size_t)g8 * 8) / 4;
    obase[0] = make_float4(acc[0].x, acc[0].y, acc[1].x, acc[1].y);
    obase[1] = make_float4(acc[2].x, acc[2].y, acc[3].x, acc[3].y);
}

extern "C" void kernel_launch(void* const* d_in, const int* in_sizes, int n_in,
                              void* d_out, int out_size) {
    const float* feat   = (const float*)d_in[0];
    const float* params = (const float*)d_in[1];
    float* out          = (float*)d_out;

    dim3 grid(HW8 / TPB, NINST);   // (25, 128)
    mask_head_kernel<<<grid, TPB>>>(feat, params, out);
}